// round 1
// baseline (speedup 1.0000x reference)
#include <cuda_runtime.h>
#include <math.h>
#include <stdint.h>

#define N_ 10000
#define E_ 60000
#define D_ 3000
#define H_ 512
#define L_ 128
#define P_ 256
#define M_ 3000

#define CDIV(a,b) (((a)+(b)-1)/(b))

// ---------------- scratch (static device globals; no allocation) ----------------
__device__ __align__(16) float g_XW1[(size_t)N_ * 1024];  // [x@sW1 | x@tW1]
__device__ __align__(16) float g_H1 [(size_t)N_ * 1024];  // aggregated layer-1 (both towers)
__device__ __align__(16) float g_H2 [(size_t)N_ * 256];   // pre-agg layer-2 (pos|neg)
__device__ __align__(16) float g_REP[(size_t)N_ * 256];   // rep_pos | rep_neg
__device__ __align__(16) float g_RM [(size_t)M_ * 256];   // rep[mask] gathered (pos|neg)
__device__ __align__(16) float g_Z1 [(size_t)M_ * 512];   // proj hidden (pos|neg)
__device__ __align__(16) float g_Z  [(size_t)M_ * 256];   // pos_z | neg_z
__device__ __align__(16) float g_REC0[(size_t)N_ * 128];  // rep_pos @ e2d_W
__device__ __align__(16) float g_RA  [(size_t)N_ * 128];  // aggregated rec (L-dim)
__device__ __align__(16) float g_RAM [(size_t)M_ * 128];  // g_RA[mask]
__device__ __align__(16) float g_RECM[(size_t)M_ * D_];   // rec rows at mask nodes
__device__ float g_dinv[N_];
__device__ int   g_deg [N_];
__device__ int   g_map [N_];     // use_neg row source index (-1 -> neg_token)
__device__ unsigned char g_ismask[N_];
__device__ float g_ptW1[H_];     // pos_token @ s_W1
__device__ float g_ntW1[H_];     // neg_token @ t_W1
__device__ float g_svec[L_];
__device__ float g_wsv [L_];
__device__ float g_acc [4];      // [0]=sum log(pos_d+eps), [1]=sum log(1-neg_d+eps), [2]=feat sum

// ---------------- setup kernels ----------------
__global__ void k_init_misc() {
    int i = blockIdx.x * blockDim.x + threadIdx.x;
    if (i < N_) { g_deg[i] = 1; g_map[i] = -1; g_ismask[i] = 0; }
    if (i < 4) g_acc[i] = 0.f;
}
__global__ void k_count_deg(const int* __restrict__ ei) {
    int e = blockIdx.x * blockDim.x + threadIdx.x;
    if (e < E_) atomicAdd(&g_deg[ei[E_ + e]], 1);
}
__global__ void k_dinv() {
    int i = blockIdx.x * blockDim.x + threadIdx.x;
    if (i < N_) g_dinv[i] = rsqrtf((float)g_deg[i]);
}
__global__ void k_mask_map(const int* __restrict__ perm, const int* __restrict__ shuf) {
    int i = blockIdx.x * blockDim.x + threadIdx.x;
    if (i < M_) g_ismask[perm[i]] = 1;
    if (i < N_ - M_) g_map[perm[M_ + i]] = perm[M_ + shuf[i]];
}
// pos_token @ s_W1 and neg_token @ t_W1 (two length-D dots per output col)
__global__ void k_token_w1(const float* __restrict__ post, const float* __restrict__ negt,
                           const float* __restrict__ sW1, const float* __restrict__ tW1) {
    __shared__ float sh[128];
    int b = blockIdx.x;
    const float* tok = (b < H_) ? post : negt;
    const float* W   = (b < H_) ? sW1  : tW1;
    int c = (b < H_) ? b : b - H_;
    float s = 0.f;
    for (int d = threadIdx.x; d < D_; d += 128) s += tok[d] * W[(size_t)d * H_ + c];
    sh[threadIdx.x] = s; __syncthreads();
    for (int o = 64; o > 0; o >>= 1) { if (threadIdx.x < o) sh[threadIdx.x] += sh[threadIdx.x + o]; __syncthreads(); }
    if (threadIdx.x == 0) { if (b < H_) g_ptW1[c] = sh[0]; else g_ntW1[c] = sh[0]; }
}

// ---------------- generic SGEMM: C[M,Nc] = A[M,K] @ B[K,Nc] (+bias)(+prelu) ----------------
// 128x128 tile, BK=8, 256 threads, 8x8 per thread, float4 global+shared access.
__global__ void __launch_bounds__(256, 1) k_sgemm(
    int Mr, int Nc, int K,
    const float* __restrict__ A, int lda,
    const float* __restrict__ B, int ldb,
    float* __restrict__ C, int ldc,
    const float* __restrict__ bias,
    const float* __restrict__ alpha)
{
    __shared__ float As[8][128];
    __shared__ float Bs[8][128];
    int m0 = blockIdx.y * 128, n0 = blockIdx.x * 128;
    int tid = threadIdx.x;
    int arow = tid >> 1, acol4 = (tid & 1) * 4;   // A: 128 rows x 8 k
    int brow = tid >> 5, bcol = (tid & 31) * 4;   // B: 8 k x 128 cols
    int tx = tid & 15, ty = tid >> 4;
    float acc[8][8];
    #pragma unroll
    for (int i = 0; i < 8; i++)
        #pragma unroll
        for (int j = 0; j < 8; j++) acc[i][j] = 0.f;

    for (int k0 = 0; k0 < K; k0 += 8) {
        float4 av = make_float4(0.f, 0.f, 0.f, 0.f);
        int gr = m0 + arow;
        if (gr < Mr) av = *reinterpret_cast<const float4*>(A + (size_t)gr * lda + k0 + acol4);
        As[acol4 + 0][arow] = av.x; As[acol4 + 1][arow] = av.y;
        As[acol4 + 2][arow] = av.z; As[acol4 + 3][arow] = av.w;
        float4 bv = make_float4(0.f, 0.f, 0.f, 0.f);
        int gc = n0 + bcol;
        if (gc < Nc) bv = *reinterpret_cast<const float4*>(B + (size_t)(k0 + brow) * ldb + gc);
        *reinterpret_cast<float4*>(&Bs[brow][bcol]) = bv;
        __syncthreads();
        #pragma unroll
        for (int k = 0; k < 8; k++) {
            float4 a0 = *reinterpret_cast<float4*>(&As[k][ty * 8]);
            float4 a1 = *reinterpret_cast<float4*>(&As[k][ty * 8 + 4]);
            float4 b0 = *reinterpret_cast<float4*>(&Bs[k][tx * 8]);
            float4 b1 = *reinterpret_cast<float4*>(&Bs[k][tx * 8 + 4]);
            float ar[8] = {a0.x, a0.y, a0.z, a0.w, a1.x, a1.y, a1.z, a1.w};
            float br[8] = {b0.x, b0.y, b0.z, b0.w, b1.x, b1.y, b1.z, b1.w};
            #pragma unroll
            for (int i = 0; i < 8; i++)
                #pragma unroll
                for (int j = 0; j < 8; j++) acc[i][j] += ar[i] * br[j];
        }
        __syncthreads();
    }
    float a = (alpha != nullptr) ? *alpha : 0.f;
    bool doprelu = (alpha != nullptr);
    #pragma unroll
    for (int i = 0; i < 8; i++) {
        int gm = m0 + ty * 8 + i; if (gm >= Mr) continue;
        #pragma unroll
        for (int j = 0; j < 8; j++) {
            int gn = n0 + tx * 8 + j; if (gn >= Nc) continue;
            float v = acc[i][j];
            if (bias) v += bias[gn];
            if (doprelu) v = (v >= 0.f) ? v : a * v;
            C[(size_t)gm * ldc + gn] = v;
        }
    }
}

// ---------------- layer-1 aggregation (1024 channels: pos|neg towers) ----------------
__device__ __forceinline__ float h1_src(int i, int c) {
    if (c < H_) {
        float v = g_XW1[(size_t)i * 1024 + c];
        if (g_ismask[i]) v += g_ptW1[c];
        return v;
    } else {
        int mp = g_map[i];
        int cc = c - H_;
        return (mp >= 0) ? g_XW1[(size_t)mp * 1024 + H_ + cc] : g_ntW1[cc];
    }
}
__global__ void k_agg1_self() {
    int idx = blockIdx.x * blockDim.x + threadIdx.x;
    if (idx >= N_ * 1024) return;
    int i = idx >> 10, c = idx & 1023;
    float di = g_dinv[i];
    g_H1[idx] = di * di * h1_src(i, c);
}
__global__ void k_agg1_edges(const int* __restrict__ ei) {
    int idx = blockIdx.x * blockDim.x + threadIdx.x;
    if (idx >= E_ * 1024) return;
    int e = idx >> 10, c = idx & 1023;
    int s = ei[e], d = ei[E_ + e];
    float w = g_dinv[s] * g_dinv[d];
    atomicAdd(&g_H1[(size_t)d * 1024 + c], w * h1_src(s, c));
}
__global__ void k_bias_prelu1(const float* __restrict__ sb1, const float* __restrict__ sa,
                              const float* __restrict__ tb1, const float* __restrict__ ta) {
    int idx = blockIdx.x * blockDim.x + threadIdx.x;
    if (idx >= N_ * 1024) return;
    int c = idx & 1023;
    float b, a;
    if (c < H_) { b = sb1[c]; a = *sa; } else { b = tb1[c - H_]; a = *ta; }
    float v = g_H1[idx] + b;
    g_H1[idx] = (v >= 0.f) ? v : a * v;
}

// ---------------- layer-2 aggregation (256 channels) ----------------
__global__ void k_agg2_self() {
    int idx = blockIdx.x * blockDim.x + threadIdx.x;
    if (idx >= N_ * 256) return;
    int i = idx >> 8;
    float di = g_dinv[i];
    g_REP[idx] = di * di * g_H2[idx];
}
__global__ void k_agg2_edges(const int* __restrict__ ei) {
    int idx = blockIdx.x * blockDim.x + threadIdx.x;
    if (idx >= E_ * 256) return;
    int e = idx >> 8, c = idx & 255;
    int s = ei[e], d = ei[E_ + e];
    float w = g_dinv[s] * g_dinv[d];
    atomicAdd(&g_REP[(size_t)d * 256 + c], w * g_H2[(size_t)s * 256 + c]);
}
__global__ void k_bias_prelu2(const float* __restrict__ sb2, const float* __restrict__ sa,
                              const float* __restrict__ tb2, const float* __restrict__ ta) {
    int idx = blockIdx.x * blockDim.x + threadIdx.x;
    if (idx >= N_ * 256) return;
    int c = idx & 255;
    float b, a;
    if (c < L_) { b = sb2[c]; a = *sa; } else { b = tb2[c - L_]; a = *ta; }
    float v = g_REP[idx] + b;
    g_REP[idx] = (v >= 0.f) ? v : a * v;
}
__global__ void k_gather_rm(const int* __restrict__ perm) {
    int idx = blockIdx.x * blockDim.x + threadIdx.x;
    if (idx >= M_ * 256) return;
    int m = idx >> 8, c = idx & 255;
    g_RM[idx] = g_REP[(size_t)perm[m] * 256 + c];
}

// ---------------- DGI ----------------
__global__ void k_colmean_sigmoid() {
    __shared__ float sh[128];
    int c = blockIdx.x;
    float s = 0.f;
    for (int m = threadIdx.x; m < M_; m += 128) s += g_Z[(size_t)m * 256 + c];
    sh[threadIdx.x] = s; __syncthreads();
    for (int o = 64; o > 0; o >>= 1) { if (threadIdx.x < o) sh[threadIdx.x] += sh[threadIdx.x + o]; __syncthreads(); }
    if (threadIdx.x == 0) g_svec[c] = 1.f / (1.f + expf(-(sh[0] / (float)M_)));
}
__global__ void k_ws(const float* __restrict__ dgiW) {
    int i = threadIdx.x;
    float s = 0.f;
    for (int j = 0; j < L_; j++) s += dgiW[(size_t)i * L_ + j] * g_svec[j];
    g_wsv[i] = s;
}
__global__ void k_dgi() {
    int gid = blockIdx.x * blockDim.x + threadIdx.x;
    int w = gid >> 5, lane = gid & 31;
    if (w >= 2 * M_) return;
    int neg = (w >= M_);
    int m = neg ? (w - M_) : w;
    size_t base = (size_t)m * 256 + (neg ? L_ : 0);
    float dot = 0.f;
    for (int j = lane; j < L_; j += 32) dot += g_Z[base + j] * g_wsv[j];
    #pragma unroll
    for (int o = 16; o > 0; o >>= 1) dot += __shfl_down_sync(0xffffffffu, dot, o);
    if (lane == 0) {
        float sg = 1.f / (1.f + expf(-dot));
        float t = neg ? logf(1.f - sg + 1e-15f) : logf(sg + 1e-15f);
        atomicAdd(&g_acc[neg ? 1 : 0], t);
    }
}

// ---------------- decoder aggregation (aggregate in L=128 first, project mask rows only) ----------------
__global__ void k_rec_self() {
    int idx = blockIdx.x * blockDim.x + threadIdx.x;
    if (idx >= N_ * 128) return;
    int i = idx >> 7;
    float di = g_dinv[i];
    g_RA[idx] = g_ismask[i] ? 0.f : di * di * g_REC0[idx];
}
__global__ void k_rec_edges(const int* __restrict__ ei) {
    int idx = blockIdx.x * blockDim.x + threadIdx.x;
    if (idx >= E_ * 128) return;
    int e = idx >> 7, c = idx & 127;
    int s = ei[e], d = ei[E_ + e];
    if (g_ismask[s]) return;
    float w = g_dinv[s] * g_dinv[d];
    atomicAdd(&g_RA[(size_t)d * 128 + c], w * g_REC0[(size_t)s * 128 + c]);
}
__global__ void k_gather_ram(const int* __restrict__ perm) {
    int idx = blockIdx.x * blockDim.x + threadIdx.x;
    if (idx >= M_ * 128) return;
    int m = idx >> 7, c = idx & 127;
    g_RAM[idx] = g_RA[(size_t)perm[m] * 128 + c];
}

// ---------------- feature (cosine) loss ----------------
__global__ void k_feat(const float* __restrict__ x, const int* __restrict__ perm) {
    __shared__ float shd[256], shx[256], shr[256];
    int m = blockIdx.x;
    int node = perm[m];
    const float* xr = x + (size_t)node * D_;
    const float* rr = g_RECM + (size_t)m * D_;
    float dt = 0.f, nx = 0.f, nr = 0.f;
    for (int d = threadIdx.x; d < D_; d += 256) {
        float a = xr[d], b = rr[d];
        dt += a * b; nx += a * a; nr += b * b;
    }
    shd[threadIdx.x] = dt; shx[threadIdx.x] = nx; shr[threadIdx.x] = nr;
    __syncthreads();
    for (int o = 128; o > 0; o >>= 1) {
        if (threadIdx.x < o) {
            shd[threadIdx.x] += shd[threadIdx.x + o];
            shx[threadIdx.x] += shx[threadIdx.x + o];
            shr[threadIdx.x] += shr[threadIdx.x + o];
        }
        __syncthreads();
    }
    if (threadIdx.x == 0) {
        float nxs = fmaxf(sqrtf(shx[0]), 1e-12f);
        float nrs = fmaxf(sqrtf(shr[0]), 1e-12f);
        float cs = shd[0] / (nxs * nrs);
        float t = 1.f - cs;
        atomicAdd(&g_acc[2], t * t);
    }
}
__global__ void k_final(float* __restrict__ out) {
    out[0] = g_acc[2] / (float)M_;
    out[1] = -(g_acc[0] + g_acc[1]) / (float)M_;
}

// ---------------- launch ----------------
extern "C" void kernel_launch(void* const* d_in, const int* in_sizes, int n_in,
                              void* d_out, int out_size) {
    const float* x    = (const float*)d_in[0];
    const int*   ei   = (const int*)  d_in[1];
    const int*   perm = (const int*)  d_in[2];
    const int*   shuf = (const int*)  d_in[3];
    const float* sW1  = (const float*)d_in[4];
    const float* sb1  = (const float*)d_in[5];
    const float* sa   = (const float*)d_in[6];
    const float* sW2  = (const float*)d_in[7];
    const float* sb2  = (const float*)d_in[8];
    const float* tW1  = (const float*)d_in[9];
    const float* tb1  = (const float*)d_in[10];
    const float* ta   = (const float*)d_in[11];
    const float* tW2  = (const float*)d_in[12];
    const float* tb2  = (const float*)d_in[13];
    const float* pW1  = (const float*)d_in[14];
    const float* pb1  = (const float*)d_in[15];
    const float* pa   = (const float*)d_in[16];
    const float* pW2  = (const float*)d_in[17];
    const float* pb2  = (const float*)d_in[18];
    const float* tpW1 = (const float*)d_in[19];
    const float* tpb1 = (const float*)d_in[20];
    const float* tpa  = (const float*)d_in[21];
    const float* tpW2 = (const float*)d_in[22];
    const float* tpb2 = (const float*)d_in[23];
    const float* dgiW = (const float*)d_in[24];
    const float* post = (const float*)d_in[25];
    const float* negt = (const float*)d_in[26];
    const float* e2d  = (const float*)d_in[27];
    const float* dW   = (const float*)d_in[28];
    const float* db   = (const float*)d_in[29];
    float* out = (float*)d_out;

    float *pXW1, *pH1, *pH2, *pREP, *pRM, *pZ1, *pZ, *pREC0, *pRAM, *pRECM;
    cudaGetSymbolAddress((void**)&pXW1,  g_XW1);
    cudaGetSymbolAddress((void**)&pH1,   g_H1);
    cudaGetSymbolAddress((void**)&pH2,   g_H2);
    cudaGetSymbolAddress((void**)&pREP,  g_REP);
    cudaGetSymbolAddress((void**)&pRM,   g_RM);
    cudaGetSymbolAddress((void**)&pZ1,   g_Z1);
    cudaGetSymbolAddress((void**)&pZ,    g_Z);
    cudaGetSymbolAddress((void**)&pREC0, g_REC0);
    cudaGetSymbolAddress((void**)&pRAM,  g_RAM);
    cudaGetSymbolAddress((void**)&pRECM, g_RECM);

    auto gemm = [&](int Mr, int Nc, int K, const float* A, int lda,
                    const float* B, int ldb, float* C, int ldc,
                    const float* bias, const float* alpha) {
        dim3 grid(CDIV(Nc, 128), CDIV(Mr, 128));
        k_sgemm<<<grid, 256>>>(Mr, Nc, K, A, lda, B, ldb, C, ldc, bias, alpha);
    };

    k_init_misc<<<CDIV(N_, 256), 256>>>();
    k_count_deg<<<CDIV(E_, 256), 256>>>(ei);
    k_dinv<<<CDIV(N_, 256), 256>>>();
    k_mask_map<<<CDIV(N_, 256), 256>>>(perm, shuf);
    k_token_w1<<<1024, 128>>>(post, negt, sW1, tW1);

    // big matmul: x @ [s_W1 | t_W1]
    gemm(N_, H_, D_, x, D_, sW1, H_, pXW1, 1024, nullptr, nullptr);
    gemm(N_, H_, D_, x, D_, tW1, H_, pXW1 + H_, 1024, nullptr, nullptr);

    // layer-1 aggregation + bias + prelu
    k_agg1_self <<<CDIV(N_ * 1024, 256), 256>>>();
    k_agg1_edges<<<CDIV(E_ * 1024, 256), 256>>>(ei);
    k_bias_prelu1<<<CDIV(N_ * 1024, 256), 256>>>(sb1, sa, tb1, ta);

    // layer-2 matmul + aggregation + bias + prelu
    gemm(N_, L_, H_, pH1, 1024, sW2, L_, pH2, 256, nullptr, nullptr);
    gemm(N_, L_, H_, pH1 + H_, 1024, tW2, L_, pH2 + L_, 256, nullptr, nullptr);
    k_agg2_self <<<CDIV(N_ * 256, 256), 256>>>();
    k_agg2_edges<<<CDIV(E_ * 256, 256), 256>>>(ei);
    k_bias_prelu2<<<CDIV(N_ * 256, 256), 256>>>(sb2, sa, tb2, ta);

    // projections on mask rows
    k_gather_rm<<<CDIV(M_ * 256, 256), 256>>>(perm);
    gemm(M_, P_, L_, pRM, 256, pW1, P_, pZ1, 512, pb1, pa);
    gemm(M_, P_, L_, pRM + L_, 256, tpW1, P_, pZ1 + P_, 512, tpb1, tpa);
    gemm(M_, L_, P_, pZ1, 512, pW2, L_, pZ, 256, pb2, nullptr);
    gemm(M_, L_, P_, pZ1 + P_, 512, tpW2, L_, pZ + L_, 256, tpb2, nullptr);

    // DGI loss
    k_colmean_sigmoid<<<128, 128>>>();
    k_ws<<<1, 128>>>(dgiW);
    k_dgi<<<CDIV(2 * M_ * 32, 256), 256>>>();

    // decoder: rec0 = rep_pos @ e2d_W; aggregate in L-dim; project only mask rows
    gemm(N_, L_, L_, pREP, 256, e2d, L_, pREC0, 128, nullptr, nullptr);
    k_rec_self <<<CDIV(N_ * 128, 256), 256>>>();
    k_rec_edges<<<CDIV(E_ * 128, 256), 256>>>(ei);
    k_gather_ram<<<CDIV(M_ * 128, 256), 256>>>(perm);
    gemm(M_, D_, L_, pRAM, 128, dW, D_, pRECM, D_, db, nullptr);

    // feature loss + finalize
    k_feat<<<M_, 256>>>(x, perm);
    k_final<<<1, 1>>>(out);
}

// round 5
// speedup vs baseline: 2.1478x; 2.1478x over previous
#include <cuda_runtime.h>
#include <cuda_bf16.h>
#include <math.h>
#include <stdint.h>

#define N_ 10000
#define E_ 60000
#define D_ 3000
#define H_ 512
#define L_ 128
#define P_ 256
#define M_ 3000

#define KPAD 3072
#define KTOT (3*KPAD)     // 9216 B-side k extent: [Bhi | Bhi | Blo]
#define AW   (2*KPAD)     // 6144 A-side storage: [Ahi | Alo], third term wraps to Ahi
#define KITERS (KTOT/64)  // 144

#define CDIV(a,b) (((a)+(b)-1)/(b))

// ---------------- scratch (static device globals; no allocation) ----------------
__device__ __align__(16) float g_XW1[(size_t)N_ * 1024];
__device__ __align__(16) float g_H1 [(size_t)N_ * 1024];
__device__ __align__(16) float g_H2 [(size_t)N_ * 256];
__device__ __align__(16) float g_REP[(size_t)N_ * 256];
__device__ __align__(16) float g_RM [(size_t)M_ * 256];
__device__ __align__(16) float g_Z1 [(size_t)M_ * 512];
__device__ __align__(16) float g_Z  [(size_t)M_ * 256];
__device__ __align__(16) float g_REC0[(size_t)N_ * 128];
__device__ __align__(16) float g_RA  [(size_t)N_ * 128];
__device__ __align__(16) float g_RAM [(size_t)M_ * 128];
__device__ __align__(16) float g_RECM[(size_t)M_ * D_];
__device__ __align__(16) __nv_bfloat16 g_Abf[(size_t)N_ * AW];     // [Ahi | Alo]
__device__ __align__(16) __nv_bfloat16 g_Bbf[(size_t)1024 * KTOT]; // [Bhi | Bhi | Blo] rows=out col
__device__ float g_dinv[N_];
__device__ int   g_deg [N_];
__device__ int   g_map [N_];
__device__ unsigned char g_ismask[N_];
__device__ float g_ptW1[H_];
__device__ float g_ntW1[H_];
__device__ float g_svec[L_];
__device__ float g_wsv [L_];
__device__ float g_acc [4];

__device__ __forceinline__ uint32_t smem_u32(const void* p) {
    uint32_t a;
    asm("{ .reg .u64 t; cvta.to.shared.u64 t, %1; cvt.u32.u64 %0, t; }" : "=r"(a) : "l"(p));
    return a;
}
__device__ __forceinline__ void cp16(uint32_t dst_smem, const void* src) {
    asm volatile("cp.async.cg.shared.global [%0], [%1], 16;" :: "r"(dst_smem), "l"(src) : "memory");
}
__device__ __forceinline__ uint32_t swz(uint32_t off) {
    return off ^ ((off >> 3) & 0x70);
}

// ================= split-bf16 conversion =================
__global__ void k_cvtA(const float* __restrict__ x) {
    size_t idx = (size_t)blockIdx.x * blockDim.x + threadIdx.x;
    if (idx >= (size_t)N_ * KPAD) return;
    int m = (int)(idx / KPAD), k = (int)(idx % KPAD);
    float v = (k < D_) ? x[(size_t)m * D_ + k] : 0.f;
    __nv_bfloat16 hi = __float2bfloat16(v);
    __nv_bfloat16 lo = __float2bfloat16(v - __bfloat162float(hi));
    size_t base = (size_t)m * AW + k;
    g_Abf[base] = hi;
    g_Abf[base + KPAD] = lo;
}
__global__ void k_cvtB(const float* __restrict__ sW1, const float* __restrict__ tW1) {
    __shared__ float tile[32][33];
    int kb = blockIdx.x * 32, nb = blockIdx.y * 32;
    int tx = threadIdx.x, ty = threadIdx.y;   // 32 x 8
    #pragma unroll
    for (int i = 0; i < 4; i++) {
        int k0 = kb + ty + i * 8, n = nb + tx;
        float v = 0.f;
        if (k0 < D_) v = (n < H_) ? sW1[(size_t)k0 * H_ + n] : tW1[(size_t)k0 * H_ + (n - H_)];
        tile[ty + i * 8][tx] = v;
    }
    __syncthreads();
    #pragma unroll
    for (int i = 0; i < 4; i++) {
        int n = nb + ty + i * 8, k0 = kb + tx;
        float v = tile[tx][ty + i * 8];
        __nv_bfloat16 hi = __float2bfloat16(v);
        __nv_bfloat16 lo = __float2bfloat16(v - __bfloat162float(hi));
        size_t base = (size_t)n * KTOT + k0;
        g_Bbf[base] = hi;               // term0: Ahi*Bhi
        g_Bbf[base + KPAD] = hi;        // term1: Alo*Bhi
        g_Bbf[base + 2 * KPAD] = lo;    // term2: Ahi*Blo
    }
}

// ================= HMMA GEMM: C[10000,1024] = split-bf16 A @ B^T =================
// BM=128 BN=128 BK=64, 256 thr, 8 warps (2m x 4n), warp tile 64x32, double buffer cp.async.
__global__ void __launch_bounds__(256, 2) k_mma_big(float* __restrict__ C) {
    extern __shared__ char smem_raw[];
    char* sm = (char*)(((uintptr_t)smem_raw + 1023) & ~(uintptr_t)1023);
    uint32_t sA = smem_u32(sm);           // 2 x 16KB
    uint32_t sB = sA + 32768;             // 2 x 16KB
    int tid = threadIdx.x;
    int m0 = blockIdx.y * 128, n0 = blockIdx.x * 128;
    int wid = tid >> 5, lane = tid & 31;
    int wm = (wid >> 2) * 64, wn = (wid & 3) * 32;

    float acc[4][4][4];
    #pragma unroll
    for (int a = 0; a < 4; a++)
        #pragma unroll
        for (int b = 0; b < 4; b++)
            #pragma unroll
            for (int q = 0; q < 4; q++) acc[a][b][q] = 0.f;

    int lr = tid >> 3, c8 = tid & 7;

    auto load_stage = [&](int kt, int buf) {
        uint32_t Ad = sA + buf * 16384, Bd = sB + buf * 16384;
        int kk = kt * 64 + c8 * 8;
        int akb = (kk >= AW) ? kk - AW : kk;
        #pragma unroll
        for (int i = 0; i < 4; i++) {
            int row = lr + i * 32;
            int gr = m0 + row; if (gr >= N_) gr = N_ - 1;
            uint32_t off = swz(row * 128 + c8 * 16);
            cp16(Ad + off, g_Abf + (size_t)gr * AW + akb);
            cp16(Bd + off, g_Bbf + (size_t)(n0 + row) * KTOT + kk);
        }
        asm volatile("cp.async.commit_group;" ::: "memory");
    };

    load_stage(0, 0);
    for (int kt = 0; kt < KITERS; kt++) {
        int buf = kt & 1;
        if (kt + 1 < KITERS) {
            load_stage(kt + 1, buf ^ 1);
            asm volatile("cp.async.wait_group 1;" ::: "memory");
        } else {
            asm volatile("cp.async.wait_group 0;" ::: "memory");
        }
        __syncthreads();
        uint32_t Ad = sA + buf * 16384, Bd = sB + buf * 16384;
        int t = lane >> 3, r = lane & 7;
        #pragma unroll
        for (int s = 0; s < 4; s++) {
            uint32_t afr[4][4], bfr[4][2];
            #pragma unroll
            for (int mi = 0; mi < 4; mi++) {
                int row = wm + mi * 16 + (t & 1) * 8 + r;
                int kb = s * 32 + (t >> 1) * 16;
                uint32_t addr = Ad + swz(row * 128 + kb);
                asm volatile("ldmatrix.sync.aligned.m8n8.x4.shared.b16 {%0,%1,%2,%3}, [%4];"
                    : "=r"(afr[mi][0]), "=r"(afr[mi][1]), "=r"(afr[mi][2]), "=r"(afr[mi][3])
                    : "r"(addr));
            }
            #pragma unroll
            for (int nj = 0; nj < 4; nj++) {
                int row = wn + nj * 8 + (lane & 7);
                int kb = s * 32 + ((lane >> 3) & 1) * 16;
                uint32_t addr = Bd + swz(row * 128 + kb);
                asm volatile("ldmatrix.sync.aligned.m8n8.x2.shared.b16 {%0,%1}, [%2];"
                    : "=r"(bfr[nj][0]), "=r"(bfr[nj][1]) : "r"(addr));
            }
            #pragma unroll
            for (int mi = 0; mi < 4; mi++)
                #pragma unroll
                for (int nj = 0; nj < 4; nj++)
                    asm volatile(
                        "mma.sync.aligned.m16n8k16.row.col.f32.bf16.bf16.f32 "
                        "{%0,%1,%2,%3}, {%4,%5,%6,%7}, {%8,%9}, {%0,%1,%2,%3};"
                        : "+f"(acc[mi][nj][0]), "+f"(acc[mi][nj][1]),
                          "+f"(acc[mi][nj][2]), "+f"(acc[mi][nj][3])
                        : "r"(afr[mi][0]), "r"(afr[mi][1]), "r"(afr[mi][2]), "r"(afr[mi][3]),
                          "r"(bfr[nj][0]), "r"(bfr[nj][1]));
        }
        __syncthreads();
    }

    int rbase = m0 + wm + (lane >> 2);
    int cbase = n0 + wn + (lane & 3) * 2;
    #pragma unroll
    for (int mi = 0; mi < 4; mi++) {
        #pragma unroll
        for (int nj = 0; nj < 4; nj++) {
            int row = rbase + mi * 16, col = cbase + nj * 8;
            if (row < N_)
                *(float2*)(C + (size_t)row * 1024 + col) = make_float2(acc[mi][nj][0], acc[mi][nj][1]);
            if (row + 8 < N_)
                *(float2*)(C + (size_t)(row + 8) * 1024 + col) = make_float2(acc[mi][nj][2], acc[mi][nj][3]);
        }
    }
}

// ---------------- setup kernels ----------------
__global__ void k_init_misc() {
    int i = blockIdx.x * blockDim.x + threadIdx.x;
    if (i < N_) { g_deg[i] = 1; g_map[i] = -1; g_ismask[i] = 0; }
    if (i < 4) g_acc[i] = 0.f;
}
__global__ void k_count_deg(const int* __restrict__ ei) {
    int e = blockIdx.x * blockDim.x + threadIdx.x;
    if (e < E_) atomicAdd(&g_deg[ei[E_ + e]], 1);
}
__global__ void k_dinv() {
    int i = blockIdx.x * blockDim.x + threadIdx.x;
    if (i < N_) g_dinv[i] = rsqrtf((float)g_deg[i]);
}
__global__ void k_mask_map(const int* __restrict__ perm, const int* __restrict__ shuf) {
    int i = blockIdx.x * blockDim.x + threadIdx.x;
    if (i < M_) g_ismask[perm[i]] = 1;
    if (i < N_ - M_) g_map[perm[M_ + i]] = perm[M_ + shuf[i]];
}
__global__ void k_token_w1(const float* __restrict__ post, const float* __restrict__ negt,
                           const float* __restrict__ sW1, const float* __restrict__ tW1) {
    __shared__ float sh[128];
    int b = blockIdx.x;
    const float* tok = (b < H_) ? post : negt;
    const float* W   = (b < H_) ? sW1  : tW1;
    int c = (b < H_) ? b : b - H_;
    float s = 0.f;
    for (int d = threadIdx.x; d < D_; d += 128) s += tok[d] * W[(size_t)d * H_ + c];
    sh[threadIdx.x] = s; __syncthreads();
    for (int o = 64; o > 0; o >>= 1) { if (threadIdx.x < o) sh[threadIdx.x] += sh[threadIdx.x + o]; __syncthreads(); }
    if (threadIdx.x == 0) { if (b < H_) g_ptW1[c] = sh[0]; else g_ntW1[c] = sh[0]; }
}

// ---------------- generic fp32 SGEMM (small matmuls) ----------------
__global__ void __launch_bounds__(256, 1) k_sgemm(
    int Mr, int Nc, int K,
    const float* __restrict__ A, int lda,
    const float* __restrict__ B, int ldb,
    float* __restrict__ C, int ldc,
    const float* __restrict__ bias,
    const float* __restrict__ alpha)
{
    __shared__ float As[8][128];
    __shared__ float Bs[8][128];
    int m0 = blockIdx.y * 128, n0 = blockIdx.x * 128;
    int tid = threadIdx.x;
    int arow = tid >> 1, acol4 = (tid & 1) * 4;
    int brow = tid >> 5, bcol = (tid & 31) * 4;
    int tx = tid & 15, ty = tid >> 4;
    float acc[8][8];
    #pragma unroll
    for (int i = 0; i < 8; i++)
        #pragma unroll
        for (int j = 0; j < 8; j++) acc[i][j] = 0.f;

    for (int k0 = 0; k0 < K; k0 += 8) {
        float4 av = make_float4(0.f, 0.f, 0.f, 0.f);
        int gr = m0 + arow;
        if (gr < Mr) av = *reinterpret_cast<const float4*>(A + (size_t)gr * lda + k0 + acol4);
        As[acol4 + 0][arow] = av.x; As[acol4 + 1][arow] = av.y;
        As[acol4 + 2][arow] = av.z; As[acol4 + 3][arow] = av.w;
        float4 bv = make_float4(0.f, 0.f, 0.f, 0.f);
        int gc = n0 + bcol;
        if (gc < Nc) bv = *reinterpret_cast<const float4*>(B + (size_t)(k0 + brow) * ldb + gc);
        *reinterpret_cast<float4*>(&Bs[brow][bcol]) = bv;
        __syncthreads();
        #pragma unroll
        for (int k = 0; k < 8; k++) {
            float4 a0 = *reinterpret_cast<float4*>(&As[k][ty * 8]);
            float4 a1 = *reinterpret_cast<float4*>(&As[k][ty * 8 + 4]);
            float4 b0 = *reinterpret_cast<float4*>(&Bs[k][tx * 8]);
            float4 b1 = *reinterpret_cast<float4*>(&Bs[k][tx * 8 + 4]);
            float ar[8] = {a0.x, a0.y, a0.z, a0.w, a1.x, a1.y, a1.z, a1.w};
            float br[8] = {b0.x, b0.y, b0.z, b0.w, b1.x, b1.y, b1.z, b1.w};
            #pragma unroll
            for (int i = 0; i < 8; i++)
                #pragma unroll
                for (int j = 0; j < 8; j++) acc[i][j] += ar[i] * br[j];
        }
        __syncthreads();
    }
    float a = (alpha != nullptr) ? *alpha : 0.f;
    bool doprelu = (alpha != nullptr);
    #pragma unroll
    for (int i = 0; i < 8; i++) {
        int gm = m0 + ty * 8 + i; if (gm >= Mr) continue;
        #pragma unroll
        for (int j = 0; j < 8; j++) {
            int gn = n0 + tx * 8 + j; if (gn >= Nc) continue;
            float v = acc[i][j];
            if (bias) v += bias[gn];
            if (doprelu) v = (v >= 0.f) ? v : a * v;
            C[(size_t)gm * ldc + gn] = v;
        }
    }
}

// ---------------- layer-1 aggregation ----------------
__device__ __forceinline__ float h1_src(int i, int c) {
    if (c < H_) {
        float v = g_XW1[(size_t)i * 1024 + c];
        if (g_ismask[i]) v += g_ptW1[c];
        return v;
    } else {
        int mp = g_map[i];
        int cc = c - H_;
        return (mp >= 0) ? g_XW1[(size_t)mp * 1024 + H_ + cc] : g_ntW1[cc];
    }
}
__global__ void k_agg1_self() {
    int idx = blockIdx.x * blockDim.x + threadIdx.x;
    if (idx >= N_ * 1024) return;
    int i = idx >> 10, c = idx & 1023;
    float di = g_dinv[i];
    g_H1[idx] = di * di * h1_src(i, c);
}
__global__ void k_agg1_edges(const int* __restrict__ ei) {
    int idx = blockIdx.x * blockDim.x + threadIdx.x;
    if (idx >= E_ * 1024) return;
    int e = idx >> 10, c = idx & 1023;
    int s = ei[e], d = ei[E_ + e];
    float w = g_dinv[s] * g_dinv[d];
    atomicAdd(&g_H1[(size_t)d * 1024 + c], w * h1_src(s, c));
}
__global__ void k_bias_prelu1(const float* __restrict__ sb1, const float* __restrict__ sa,
                              const float* __restrict__ tb1, const float* __restrict__ ta) {
    int idx = blockIdx.x * blockDim.x + threadIdx.x;
    if (idx >= N_ * 1024) return;
    int c = idx & 1023;
    float b, a;
    if (c < H_) { b = sb1[c]; a = *sa; } else { b = tb1[c - H_]; a = *ta; }
    float v = g_H1[idx] + b;
    g_H1[idx] = (v >= 0.f) ? v : a * v;
}

// ---------------- layer-2 aggregation ----------------
__global__ void k_agg2_self() {
    int idx = blockIdx.x * blockDim.x + threadIdx.x;
    if (idx >= N_ * 256) return;
    int i = idx >> 8;
    float di = g_dinv[i];
    g_REP[idx] = di * di * g_H2[idx];
}
__global__ void k_agg2_edges(const int* __restrict__ ei) {
    int idx = blockIdx.x * blockDim.x + threadIdx.x;
    if (idx >= E_ * 256) return;
    int e = idx >> 8, c = idx & 255;
    int s = ei[e], d = ei[E_ + e];
    float w = g_dinv[s] * g_dinv[d];
    atomicAdd(&g_REP[(size_t)d * 256 + c], w * g_H2[(size_t)s * 256 + c]);
}
__global__ void k_bias_prelu2(const float* __restrict__ sb2, const float* __restrict__ sa,
                              const float* __restrict__ tb2, const float* __restrict__ ta) {
    int idx = blockIdx.x * blockDim.x + threadIdx.x;
    if (idx >= N_ * 256) return;
    int c = idx & 255;
    float b, a;
    if (c < L_) { b = sb2[c]; a = *sa; } else { b = tb2[c - L_]; a = *ta; }
    float v = g_REP[idx] + b;
    g_REP[idx] = (v >= 0.f) ? v : a * v;
}
__global__ void k_gather_rm(const int* __restrict__ perm) {
    int idx = blockIdx.x * blockDim.x + threadIdx.x;
    if (idx >= M_ * 256) return;
    int m = idx >> 8, c = idx & 255;
    g_RM[idx] = g_REP[(size_t)perm[m] * 256 + c];
}

// ---------------- DGI ----------------
__global__ void k_colmean_sigmoid() {
    __shared__ float sh[128];
    int c = blockIdx.x;
    float s = 0.f;
    for (int m = threadIdx.x; m < M_; m += 128) s += g_Z[(size_t)m * 256 + c];
    sh[threadIdx.x] = s; __syncthreads();
    for (int o = 64; o > 0; o >>= 1) { if (threadIdx.x < o) sh[threadIdx.x] += sh[threadIdx.x + o]; __syncthreads(); }
    if (threadIdx.x == 0) g_svec[c] = 1.f / (1.f + expf(-(sh[0] / (float)M_)));
}
__global__ void k_ws(const float* __restrict__ dgiW) {
    int i = threadIdx.x;
    float s = 0.f;
    for (int j = 0; j < L_; j++) s += dgiW[(size_t)i * L_ + j] * g_svec[j];
    g_wsv[i] = s;
}
__global__ void k_dgi() {
    int gid = blockIdx.x * blockDim.x + threadIdx.x;
    int w = gid >> 5, lane = gid & 31;
    if (w >= 2 * M_) return;
    int neg = (w >= M_);
    int m = neg ? (w - M_) : w;
    size_t base = (size_t)m * 256 + (neg ? L_ : 0);
    float dot = 0.f;
    for (int j = lane; j < L_; j += 32) dot += g_Z[base + j] * g_wsv[j];
    #pragma unroll
    for (int o = 16; o > 0; o >>= 1) dot += __shfl_down_sync(0xffffffffu, dot, o);
    if (lane == 0) {
        float sg = 1.f / (1.f + expf(-dot));
        float t = neg ? logf(1.f - sg + 1e-15f) : logf(sg + 1e-15f);
        atomicAdd(&g_acc[neg ? 1 : 0], t);
    }
}

// ---------------- decoder aggregation ----------------
__global__ void k_rec_self() {
    int idx = blockIdx.x * blockDim.x + threadIdx.x;
    if (idx >= N_ * 128) return;
    int i = idx >> 7;
    float di = g_dinv[i];
    g_RA[idx] = g_ismask[i] ? 0.f : di * di * g_REC0[idx];
}
__global__ void k_rec_edges(const int* __restrict__ ei) {
    int idx = blockIdx.x * blockDim.x + threadIdx.x;
    if (idx >= E_ * 128) return;
    int e = idx >> 7, c = idx & 127;
    int s = ei[e], d = ei[E_ + e];
    if (g_ismask[s]) return;
    float w = g_dinv[s] * g_dinv[d];
    atomicAdd(&g_RA[(size_t)d * 128 + c], w * g_REC0[(size_t)s * 128 + c]);
}
__global__ void k_gather_ram(const int* __restrict__ perm) {
    int idx = blockIdx.x * blockDim.x + threadIdx.x;
    if (idx >= M_ * 128) return;
    int m = idx >> 7, c = idx & 127;
    g_RAM[idx] = g_RA[(size_t)perm[m] * 128 + c];
}

// ---------------- feature (cosine) loss ----------------
__global__ void k_feat(const float* __restrict__ x, const int* __restrict__ perm) {
    __shared__ float shd[256], shx[256], shr[256];
    int m = blockIdx.x;
    int node = perm[m];
    const float* xr = x + (size_t)node * D_;
    const float* rr = g_RECM + (size_t)m * D_;
    float dt = 0.f, nx = 0.f, nr = 0.f;
    for (int d = threadIdx.x; d < D_; d += 256) {
        float a = xr[d], b = rr[d];
        dt += a * b; nx += a * a; nr += b * b;
    }
    shd[threadIdx.x] = dt; shx[threadIdx.x] = nx; shr[threadIdx.x] = nr;
    __syncthreads();
    for (int o = 128; o > 0; o >>= 1) {
        if (threadIdx.x < o) {
            shd[threadIdx.x] += shd[threadIdx.x + o];
            shx[threadIdx.x] += shx[threadIdx.x + o];
            shr[threadIdx.x] += shr[threadIdx.x + o];
        }
        __syncthreads();
    }
    if (threadIdx.x == 0) {
        float nxs = fmaxf(sqrtf(shx[0]), 1e-12f);
        float nrs = fmaxf(sqrtf(shr[0]), 1e-12f);
        float cs = shd[0] / (nxs * nrs);
        float t = 1.f - cs;
        atomicAdd(&g_acc[2], t * t);
    }
}
__global__ void k_final(float* __restrict__ out) {
    out[0] = g_acc[2] / (float)M_;
    out[1] = -(g_acc[0] + g_acc[1]) / (float)M_;
}

// ---------------- launch ----------------
extern "C" void kernel_launch(void* const* d_in, const int* in_sizes, int n_in,
                              void* d_out, int out_size) {
    const float* x    = (const float*)d_in[0];
    const int*   ei   = (const int*)  d_in[1];
    const int*   perm = (const int*)  d_in[2];
    const int*   shuf = (const int*)  d_in[3];
    const float* sW1  = (const float*)d_in[4];
    const float* sb1  = (const float*)d_in[5];
    const float* sa   = (const float*)d_in[6];
    const float* sW2  = (const float*)d_in[7];
    const float* sb2  = (const float*)d_in[8];
    const float* tW1  = (const float*)d_in[9];
    const float* tb1  = (const float*)d_in[10];
    const float* ta   = (const float*)d_in[11];
    const float* tW2  = (const float*)d_in[12];
    const float* tb2  = (const float*)d_in[13];
    const float* pW1  = (const float*)d_in[14];
    const float* pb1  = (const float*)d_in[15];
    const float* pa   = (const float*)d_in[16];
    const float* pW2  = (const float*)d_in[17];
    const float* pb2  = (const float*)d_in[18];
    const float* tpW1 = (const float*)d_in[19];
    const float* tpb1 = (const float*)d_in[20];
    const float* tpa  = (const float*)d_in[21];
    const float* tpW2 = (const float*)d_in[22];
    const float* tpb2 = (const float*)d_in[23];
    const float* dgiW = (const float*)d_in[24];
    const float* post = (const float*)d_in[25];
    const float* negt = (const float*)d_in[26];
    const float* e2d  = (const float*)d_in[27];
    const float* dW   = (const float*)d_in[28];
    const float* db   = (const float*)d_in[29];
    float* out = (float*)d_out;

    float *pXW1, *pH1, *pH2, *pREP, *pRM, *pZ1, *pZ, *pREC0, *pRAM, *pRECM;
    cudaGetSymbolAddress((void**)&pXW1,  g_XW1);
    cudaGetSymbolAddress((void**)&pH1,   g_H1);
    cudaGetSymbolAddress((void**)&pH2,   g_H2);
    cudaGetSymbolAddress((void**)&pREP,  g_REP);
    cudaGetSymbolAddress((void**)&pRM,   g_RM);
    cudaGetSymbolAddress((void**)&pZ1,   g_Z1);
    cudaGetSymbolAddress((void**)&pZ,    g_Z);
    cudaGetSymbolAddress((void**)&pREC0, g_REC0);
    cudaGetSymbolAddress((void**)&pRAM,  g_RAM);
    cudaGetSymbolAddress((void**)&pRECM, g_RECM);

    cudaFuncSetAttribute(k_mma_big, cudaFuncAttributeMaxDynamicSharedMemorySize, 66560);

    auto gemm = [&](int Mr, int Nc, int K, const float* A, int lda,
                    const float* B, int ldb, float* C, int ldc,
                    const float* bias, const float* alpha) {
        dim3 grid(CDIV(Nc, 128), CDIV(Mr, 128));
        k_sgemm<<<grid, 256>>>(Mr, Nc, K, A, lda, B, ldb, C, ldc, bias, alpha);
    };

    k_init_misc<<<CDIV(N_, 256), 256>>>();
    k_count_deg<<<CDIV(E_, 256), 256>>>(ei);
    k_dinv<<<CDIV(N_, 256), 256>>>();
    k_mask_map<<<CDIV(N_, 256), 256>>>(perm, shuf);
    k_token_w1<<<1024, 128>>>(post, negt, sW1, tW1);

    // big matmul: x @ [s_W1 | t_W1] via split-bf16 HMMA
    k_cvtA<<<(int)CDIV((size_t)N_ * KPAD, 256), 256>>>(x);
    k_cvtB<<<dim3(KPAD / 32, 1024 / 32), dim3(32, 8)>>>(sW1, tW1);
    k_mma_big<<<dim3(1024 / 128, CDIV(N_, 128)), 256, 66560>>>(pXW1);

    // layer-1 aggregation + bias + prelu
    k_agg1_self <<<CDIV(N_ * 1024, 256), 256>>>();
    k_agg1_edges<<<CDIV(E_ * 1024, 256), 256>>>(ei);
    k_bias_prelu1<<<CDIV(N_ * 1024, 256), 256>>>(sb1, sa, tb1, ta);

    // layer-2 matmul + aggregation + bias + prelu
    gemm(N_, L_, H_, pH1, 1024, sW2, L_, pH2, 256, nullptr, nullptr);
    gemm(N_, L_, H_, pH1 + H_, 1024, tW2, L_, pH2 + L_, 256, nullptr, nullptr);
    k_agg2_self <<<CDIV(N_ * 256, 256), 256>>>();
    k_agg2_edges<<<CDIV(E_ * 256, 256), 256>>>(ei);
    k_bias_prelu2<<<CDIV(N_ * 256, 256), 256>>>(sb2, sa, tb2, ta);

    // projections on mask rows
    k_gather_rm<<<CDIV(M_ * 256, 256), 256>>>(perm);
    gemm(M_, P_, L_, pRM, 256, pW1, P_, pZ1, 512, pb1, pa);
    gemm(M_, P_, L_, pRM + L_, 256, tpW1, P_, pZ1 + P_, 512, tpb1, tpa);
    gemm(M_, L_, P_, pZ1, 512, pW2, L_, pZ, 256, pb2, nullptr);
    gemm(M_, L_, P_, pZ1 + P_, 512, tpW2, L_, pZ + L_, 256, tpb2, nullptr);

    // DGI loss
    k_colmean_sigmoid<<<128, 128>>>();
    k_ws<<<1, 128>>>(dgiW);
    k_dgi<<<CDIV(2 * M_ * 32, 256), 256>>>();

    // decoder
    gemm(N_, L_, L_, pREP, 256, e2d, L_, pREC0, 128, nullptr, nullptr);
    k_rec_self <<<CDIV(N_ * 128, 256), 256>>>();
    k_rec_edges<<<CDIV(E_ * 128, 256), 256>>>(ei);
    k_gather_ram<<<CDIV(M_ * 128, 256), 256>>>(perm);
    gemm(M_, D_, L_, pRAM, 128, dW, D_, pRECM, D_, db, nullptr);

    // feature loss + finalize
    k_feat<<<M_, 256>>>(x, perm);
    k_final<<<1, 1>>>(out);
}

// round 7
// speedup vs baseline: 2.3604x; 1.0990x over previous
#include <cuda_runtime.h>
#include <cuda_bf16.h>
#include <math.h>
#include <stdint.h>

#define N_ 10000
#define E_ 60000
#define D_ 3000
#define H_ 512
#define L_ 128
#define P_ 256
#define M_ 3000

#define KPAD 3072
#define KTOT (3*KPAD)     // 9216 B-side k extent: [Bhi | Bhi | Blo]
#define AW   (2*KPAD)     // 6144 A-side storage: [Ahi | Alo], third term wraps to Ahi
#define KITERS (KTOT/64)  // 144

#define CDIV(a,b) (((a)+(b)-1)/(b))

// ---------------- scratch (static device globals; no allocation) ----------------
__device__ __align__(16) float g_XW1[(size_t)N_ * 1024];
__device__ __align__(16) float g_H1 [(size_t)N_ * 1024];
__device__ __align__(16) float g_H2 [(size_t)N_ * 256];
__device__ __align__(16) float g_REP[(size_t)N_ * 256];
__device__ __align__(16) float g_RM [(size_t)M_ * 256];
__device__ __align__(16) float g_Z1 [(size_t)M_ * 512];
__device__ __align__(16) float g_Z  [(size_t)M_ * 256];
__device__ __align__(16) float g_REC0[(size_t)N_ * 128];
__device__ __align__(16) float g_RA  [(size_t)N_ * 128];
__device__ __align__(16) float g_RAM [(size_t)M_ * 128];
__device__ __align__(16) float g_RECM[(size_t)M_ * D_];
__device__ __align__(16) __nv_bfloat16 g_Abf[(size_t)N_ * AW];     // [Ahi | Alo]
__device__ __align__(16) __nv_bfloat16 g_Bbf[(size_t)1024 * KTOT]; // [Bhi | Bhi | Blo] rows=out col
__device__ float g_dinv[N_];
__device__ int   g_deg [N_];
__device__ int   g_map [N_];
__device__ unsigned char g_ismask[N_];
__device__ __align__(16) float g_ptW1[H_];
__device__ __align__(16) float g_ntW1[H_];
__device__ float g_svec[L_];
__device__ float g_wsv [L_];
__device__ float g_acc [4];

__device__ __forceinline__ uint32_t smem_u32(const void* p) {
    uint32_t a;
    asm("{ .reg .u64 t; cvta.to.shared.u64 t, %1; cvt.u32.u64 %0, t; }" : "=r"(a) : "l"(p));
    return a;
}
__device__ __forceinline__ void cp16(uint32_t dst_smem, const void* src) {
    asm volatile("cp.async.cg.shared.global [%0], [%1], 16;" :: "r"(dst_smem), "l"(src) : "memory");
}
__device__ __forceinline__ uint32_t swz(uint32_t off) {
    return off ^ ((off >> 3) & 0x70);
}
__device__ __forceinline__ void red4(float* p, float4 v) {
    asm volatile("red.global.add.v4.f32 [%0], {%1,%2,%3,%4};"
        :: "l"(p), "f"(v.x), "f"(v.y), "f"(v.z), "f"(v.w) : "memory");
}

// ================= split-bf16 conversion =================
__global__ void k_cvtA(const float* __restrict__ x) {
    size_t idx = (size_t)blockIdx.x * blockDim.x + threadIdx.x;
    if (idx >= (size_t)N_ * KPAD) return;
    int m = (int)(idx / KPAD), k = (int)(idx % KPAD);
    float v = (k < D_) ? x[(size_t)m * D_ + k] : 0.f;
    __nv_bfloat16 hi = __float2bfloat16(v);
    __nv_bfloat16 lo = __float2bfloat16(v - __bfloat162float(hi));
    size_t base = (size_t)m * AW + k;
    g_Abf[base] = hi;
    g_Abf[base + KPAD] = lo;
}
__global__ void k_cvtB(const float* __restrict__ sW1, const float* __restrict__ tW1) {
    __shared__ float tile[32][33];
    int kb = blockIdx.x * 32, nb = blockIdx.y * 32;
    int tx = threadIdx.x, ty = threadIdx.y;   // 32 x 8
    #pragma unroll
    for (int i = 0; i < 4; i++) {
        int k0 = kb + ty + i * 8, n = nb + tx;
        float v = 0.f;
        if (k0 < D_) v = (n < H_) ? sW1[(size_t)k0 * H_ + n] : tW1[(size_t)k0 * H_ + (n - H_)];
        tile[ty + i * 8][tx] = v;
    }
    __syncthreads();
    #pragma unroll
    for (int i = 0; i < 4; i++) {
        int n = nb + ty + i * 8, k0 = kb + tx;
        float v = tile[tx][ty + i * 8];
        __nv_bfloat16 hi = __float2bfloat16(v);
        __nv_bfloat16 lo = __float2bfloat16(v - __bfloat162float(hi));
        size_t base = (size_t)n * KTOT + k0;
        g_Bbf[base] = hi;
        g_Bbf[base + KPAD] = hi;
        g_Bbf[base + 2 * KPAD] = lo;
    }
}

// ================= HMMA GEMM: C[10000,1024] = split-bf16 A @ B^T =================
// BM=128 BN=256 BK=64, 512 thr, 16 warps (2m x 8n), warp tile 64x32, double buffer cp.async.
__global__ void __launch_bounds__(512, 1) k_mma_big(float* __restrict__ C) {
    extern __shared__ char smem_raw[];
    char* sm = (char*)(((uintptr_t)smem_raw + 1023) & ~(uintptr_t)1023);
    uint32_t sA = smem_u32(sm);           // 2 x 16KB
    uint32_t sB = sA + 32768;             // 2 x 32KB
    int tid = threadIdx.x;
    int m0 = blockIdx.y * 128, n0 = blockIdx.x * 256;
    int wid = tid >> 5, lane = tid & 31;
    int wm = (wid >> 3) * 64, wn = (wid & 7) * 32;

    float acc[4][4][4];
    #pragma unroll
    for (int a = 0; a < 4; a++)
        #pragma unroll
        for (int b = 0; b < 4; b++)
            #pragma unroll
            for (int q = 0; q < 4; q++) acc[a][b][q] = 0.f;

    int lr = tid >> 3, c8 = tid & 7;   // 64 rows per pass, 8 x 16B per row

    auto load_stage = [&](int kt, int buf) {
        uint32_t Ad = sA + buf * 16384, Bd = sB + buf * 32768;
        int kk = kt * 64 + c8 * 8;
        int akb = (kk >= AW) ? kk - AW : kk;
        #pragma unroll
        for (int i = 0; i < 2; i++) {          // A: 128 rows
            int row = lr + i * 64;
            int gr = m0 + row; if (gr >= N_) gr = N_ - 1;
            cp16(Ad + swz(row * 128 + c8 * 16), g_Abf + (size_t)gr * AW + akb);
        }
        #pragma unroll
        for (int i = 0; i < 4; i++) {          // B: 256 rows
            int row = lr + i * 64;
            cp16(Bd + swz(row * 128 + c8 * 16), g_Bbf + (size_t)(n0 + row) * KTOT + kk);
        }
        asm volatile("cp.async.commit_group;" ::: "memory");
    };

    load_stage(0, 0);
    for (int kt = 0; kt < KITERS; kt++) {
        int buf = kt & 1;
        if (kt + 1 < KITERS) {
            load_stage(kt + 1, buf ^ 1);
            asm volatile("cp.async.wait_group 1;" ::: "memory");
        } else {
            asm volatile("cp.async.wait_group 0;" ::: "memory");
        }
        __syncthreads();
        uint32_t Ad = sA + buf * 16384, Bd = sB + buf * 32768;
        int t = lane >> 3, r = lane & 7;
        #pragma unroll
        for (int s = 0; s < 4; s++) {
            uint32_t afr[4][4], bfr[4][2];
            #pragma unroll
            for (int mi = 0; mi < 4; mi++) {
                int row = wm + mi * 16 + (t & 1) * 8 + r;
                int kb = s * 32 + (t >> 1) * 16;
                uint32_t addr = Ad + swz(row * 128 + kb);
                asm volatile("ldmatrix.sync.aligned.m8n8.x4.shared.b16 {%0,%1,%2,%3}, [%4];"
                    : "=r"(afr[mi][0]), "=r"(afr[mi][1]), "=r"(afr[mi][2]), "=r"(afr[mi][3])
                    : "r"(addr));
            }
            #pragma unroll
            for (int nj = 0; nj < 4; nj++) {
                int row = wn + nj * 8 + (lane & 7);
                int kb = s * 32 + ((lane >> 3) & 1) * 16;
                uint32_t addr = Bd + swz(row * 128 + kb);
                asm volatile("ldmatrix.sync.aligned.m8n8.x2.shared.b16 {%0,%1}, [%2];"
                    : "=r"(bfr[nj][0]), "=r"(bfr[nj][1]) : "r"(addr));
            }
            #pragma unroll
            for (int mi = 0; mi < 4; mi++)
                #pragma unroll
                for (int nj = 0; nj < 4; nj++)
                    asm volatile(
                        "mma.sync.aligned.m16n8k16.row.col.f32.bf16.bf16.f32 "
                        "{%0,%1,%2,%3}, {%4,%5,%6,%7}, {%8,%9}, {%0,%1,%2,%3};"
                        : "+f"(acc[mi][nj][0]), "+f"(acc[mi][nj][1]),
                          "+f"(acc[mi][nj][2]), "+f"(acc[mi][nj][3])
                        : "r"(afr[mi][0]), "r"(afr[mi][1]), "r"(afr[mi][2]), "r"(afr[mi][3]),
                          "r"(bfr[nj][0]), "r"(bfr[nj][1]));
        }
        __syncthreads();
    }

    int rbase = m0 + wm + (lane >> 2);
    int cbase = n0 + wn + (lane & 3) * 2;
    #pragma unroll
    for (int mi = 0; mi < 4; mi++) {
        #pragma unroll
        for (int nj = 0; nj < 4; nj++) {
            int row = rbase + mi * 16, col = cbase + nj * 8;
            if (row < N_)
                *(float2*)(C + (size_t)row * 1024 + col) = make_float2(acc[mi][nj][0], acc[mi][nj][1]);
            if (row + 8 < N_)
                *(float2*)(C + (size_t)(row + 8) * 1024 + col) = make_float2(acc[mi][nj][2], acc[mi][nj][3]);
        }
    }
}

// ---------------- setup kernels ----------------
__global__ void k_init_misc() {
    int i = blockIdx.x * blockDim.x + threadIdx.x;
    if (i < N_) { g_deg[i] = 1; g_map[i] = -1; g_ismask[i] = 0; }
    if (i < 4) g_acc[i] = 0.f;
}
__global__ void k_count_deg(const int* __restrict__ ei) {
    int e = blockIdx.x * blockDim.x + threadIdx.x;
    if (e < E_) atomicAdd(&g_deg[ei[E_ + e]], 1);
}
__global__ void k_dinv() {
    int i = blockIdx.x * blockDim.x + threadIdx.x;
    if (i < N_) g_dinv[i] = rsqrtf((float)g_deg[i]);
}
__global__ void k_mask_map(const int* __restrict__ perm, const int* __restrict__ shuf) {
    int i = blockIdx.x * blockDim.x + threadIdx.x;
    if (i < M_) g_ismask[perm[i]] = 1;
    if (i < N_ - M_) g_map[perm[M_ + i]] = perm[M_ + shuf[i]];
}
__global__ void k_token_w1(const float* __restrict__ post, const float* __restrict__ negt,
                           const float* __restrict__ sW1, const float* __restrict__ tW1) {
    __shared__ float sh[128];
    int b = blockIdx.x;
    const float* tok = (b < H_) ? post : negt;
    const float* W   = (b < H_) ? sW1  : tW1;
    int c = (b < H_) ? b : b - H_;
    float s = 0.f;
    for (int d = threadIdx.x; d < D_; d += 128) s += tok[d] * W[(size_t)d * H_ + c];
    sh[threadIdx.x] = s; __syncthreads();
    for (int o = 64; o > 0; o >>= 1) { if (threadIdx.x < o) sh[threadIdx.x] += sh[threadIdx.x + o]; __syncthreads(); }
    if (threadIdx.x == 0) { if (b < H_) g_ptW1[c] = sh[0]; else g_ntW1[c] = sh[0]; }
}

// ---------------- generic fp32 SGEMM (small matmuls) ----------------
__global__ void __launch_bounds__(256, 2) k_sgemm(
    int Mr, int Nc, int K,
    const float* __restrict__ A, int lda,
    const float* __restrict__ B, int ldb,
    float* __restrict__ C, int ldc,
    const float* __restrict__ bias,
    const float* __restrict__ alpha)
{
    __shared__ float As[8][128];
    __shared__ float Bs[8][128];
    int m0 = blockIdx.y * 128, n0 = blockIdx.x * 128;
    int tid = threadIdx.x;
    int arow = tid >> 1, acol4 = (tid & 1) * 4;
    int brow = tid >> 5, bcol = (tid & 31) * 4;
    int tx = tid & 15, ty = tid >> 4;
    float acc[8][8];
    #pragma unroll
    for (int i = 0; i < 8; i++)
        #pragma unroll
        for (int j = 0; j < 8; j++) acc[i][j] = 0.f;

    for (int k0 = 0; k0 < K; k0 += 8) {
        float4 av = make_float4(0.f, 0.f, 0.f, 0.f);
        int gr = m0 + arow;
        if (gr < Mr) av = *reinterpret_cast<const float4*>(A + (size_t)gr * lda + k0 + acol4);
        As[acol4 + 0][arow] = av.x; As[acol4 + 1][arow] = av.y;
        As[acol4 + 2][arow] = av.z; As[acol4 + 3][arow] = av.w;
        float4 bv = make_float4(0.f, 0.f, 0.f, 0.f);
        int gc = n0 + bcol;
        if (gc < Nc) bv = *reinterpret_cast<const float4*>(B + (size_t)(k0 + brow) * ldb + gc);
        *reinterpret_cast<float4*>(&Bs[brow][bcol]) = bv;
        __syncthreads();
        #pragma unroll
        for (int k = 0; k < 8; k++) {
            float4 a0 = *reinterpret_cast<float4*>(&As[k][ty * 8]);
            float4 a1 = *reinterpret_cast<float4*>(&As[k][ty * 8 + 4]);
            float4 b0 = *reinterpret_cast<float4*>(&Bs[k][tx * 8]);
            float4 b1 = *reinterpret_cast<float4*>(&Bs[k][tx * 8 + 4]);
            float ar[8] = {a0.x, a0.y, a0.z, a0.w, a1.x, a1.y, a1.z, a1.w};
            float br[8] = {b0.x, b0.y, b0.z, b0.w, b1.x, b1.y, b1.z, b1.w};
            #pragma unroll
            for (int i = 0; i < 8; i++)
                #pragma unroll
                for (int j = 0; j < 8; j++) acc[i][j] += ar[i] * br[j];
        }
        __syncthreads();
    }
    float a = (alpha != nullptr) ? *alpha : 0.f;
    bool doprelu = (alpha != nullptr);
    #pragma unroll
    for (int i = 0; i < 8; i++) {
        int gm = m0 + ty * 8 + i; if (gm >= Mr) continue;
        #pragma unroll
        for (int j = 0; j < 8; j++) {
            int gn = n0 + tx * 8 + j; if (gn >= Nc) continue;
            float v = acc[i][j];
            if (bias) v += bias[gn];
            if (doprelu) v = (v >= 0.f) ? v : a * v;
            C[(size_t)gm * ldc + gn] = v;
        }
    }
}

// ---------------- layer-1 aggregation (vectorized, v4 reductions) ----------------
__device__ __forceinline__ float4 h1_src4(int i, int c4) {
    if (c4 < H_) {
        float4 v = *(const float4*)&g_XW1[(size_t)i * 1024 + c4];
        if (g_ismask[i]) {
            float4 t = *(const float4*)&g_ptW1[c4];
            v.x += t.x; v.y += t.y; v.z += t.z; v.w += t.w;
        }
        return v;
    } else {
        int mp = g_map[i];
        if (mp >= 0) return *(const float4*)&g_XW1[(size_t)mp * 1024 + c4];
        return *(const float4*)&g_ntW1[c4 - H_];
    }
}
__global__ void k_agg1_self() {
    int idx = blockIdx.x * blockDim.x + threadIdx.x;
    if (idx >= N_ * 256) return;
    int i = idx >> 8, c4 = (idx & 255) * 4;
    float di = g_dinv[i];
    float w = di * di;
    float4 v = h1_src4(i, c4);
    v.x *= w; v.y *= w; v.z *= w; v.w *= w;
    *(float4*)&g_H1[(size_t)i * 1024 + c4] = v;
}
__global__ void k_agg1_edges(const int* __restrict__ ei) {
    int idx = blockIdx.x * blockDim.x + threadIdx.x;
    if (idx >= E_ * 256) return;
    int e = idx >> 8, c4 = (idx & 255) * 4;
    int s = ei[e], d = ei[E_ + e];
    float w = g_dinv[s] * g_dinv[d];
    float4 v = h1_src4(s, c4);
    v.x *= w; v.y *= w; v.z *= w; v.w *= w;
    red4(&g_H1[(size_t)d * 1024 + c4], v);
}
__global__ void k_bias_prelu1(const float* __restrict__ sb1, const float* __restrict__ sa,
                              const float* __restrict__ tb1, const float* __restrict__ ta) {
    int idx = blockIdx.x * blockDim.x + threadIdx.x;
    if (idx >= N_ * 256) return;
    int c4 = (idx & 255) * 4;
    float4 b; float a;
    if (c4 < H_) { b = *(const float4*)&sb1[c4]; a = *sa; }
    else         { b = *(const float4*)&tb1[c4 - H_]; a = *ta; }
    float4 v = *(float4*)&g_H1[(size_t)idx * 4];
    v.x += b.x; v.y += b.y; v.z += b.z; v.w += b.w;
    v.x = (v.x >= 0.f) ? v.x : a * v.x;
    v.y = (v.y >= 0.f) ? v.y : a * v.y;
    v.z = (v.z >= 0.f) ? v.z : a * v.z;
    v.w = (v.w >= 0.f) ? v.w : a * v.w;
    *(float4*)&g_H1[(size_t)idx * 4] = v;
}

// ---------------- layer-2 aggregation ----------------
__global__ void k_agg2_self() {
    int idx = blockIdx.x * blockDim.x + threadIdx.x;
    if (idx >= N_ * 64) return;
    int i = idx >> 6;
    float di = g_dinv[i];
    float w = di * di;
    float4 v = *(const float4*)&g_H2[(size_t)idx * 4];
    v.x *= w; v.y *= w; v.z *= w; v.w *= w;
    *(float4*)&g_REP[(size_t)idx * 4] = v;
}
__global__ void k_agg2_edges(const int* __restrict__ ei) {
    int idx = blockIdx.x * blockDim.x + threadIdx.x;
    if (idx >= E_ * 64) return;
    int e = idx >> 6, c4 = (idx & 63) * 4;
    int s = ei[e], d = ei[E_ + e];
    float w = g_dinv[s] * g_dinv[d];
    float4 v = *(const float4*)&g_H2[(size_t)s * 256 + c4];
    v.x *= w; v.y *= w; v.z *= w; v.w *= w;
    red4(&g_REP[(size_t)d * 256 + c4], v);
}
__global__ void k_bias_prelu2(const float* __restrict__ sb2, const float* __restrict__ sa,
                              const float* __restrict__ tb2, const float* __restrict__ ta) {
    int idx = blockIdx.x * blockDim.x + threadIdx.x;
    if (idx >= N_ * 64) return;
    int c4 = (idx & 63) * 4;
    float4 b; float a;
    if (c4 < L_) { b = *(const float4*)&sb2[c4]; a = *sa; }
    else         { b = *(const float4*)&tb2[c4 - L_]; a = *ta; }
    float4 v = *(float4*)&g_REP[(size_t)idx * 4];
    v.x += b.x; v.y += b.y; v.z += b.z; v.w += b.w;
    v.x = (v.x >= 0.f) ? v.x : a * v.x;
    v.y = (v.y >= 0.f) ? v.y : a * v.y;
    v.z = (v.z >= 0.f) ? v.z : a * v.z;
    v.w = (v.w >= 0.f) ? v.w : a * v.w;
    *(float4*)&g_REP[(size_t)idx * 4] = v;
}
__global__ void k_gather_rm(const int* __restrict__ perm) {
    int idx = blockIdx.x * blockDim.x + threadIdx.x;
    if (idx >= M_ * 64) return;
    int m = idx >> 6, c4 = (idx & 63) * 4;
    *(float4*)&g_RM[(size_t)idx * 4] = *(const float4*)&g_REP[(size_t)perm[m] * 256 + c4];
}

// ---------------- DGI ----------------
__global__ void k_colmean_sigmoid() {
    __shared__ float sh[128];
    int c = blockIdx.x;
    float s = 0.f;
    for (int m = threadIdx.x; m < M_; m += 128) s += g_Z[(size_t)m * 256 + c];
    sh[threadIdx.x] = s; __syncthreads();
    for (int o = 64; o > 0; o >>= 1) { if (threadIdx.x < o) sh[threadIdx.x] += sh[threadIdx.x + o]; __syncthreads(); }
    if (threadIdx.x == 0) g_svec[c] = 1.f / (1.f + expf(-(sh[0] / (float)M_)));
}
__global__ void k_ws(const float* __restrict__ dgiW) {
    int i = threadIdx.x;
    float s = 0.f;
    for (int j = 0; j < L_; j++) s += dgiW[(size_t)i * L_ + j] * g_svec[j];
    g_wsv[i] = s;
}
__global__ void k_dgi() {
    int gid = blockIdx.x * blockDim.x + threadIdx.x;
    int w = gid >> 5, lane = gid & 31;
    if (w >= 2 * M_) return;
    int neg = (w >= M_);
    int m = neg ? (w - M_) : w;
    size_t base = (size_t)m * 256 + (neg ? L_ : 0);
    float dot = 0.f;
    for (int j = lane; j < L_; j += 32) dot += g_Z[base + j] * g_wsv[j];
    #pragma unroll
    for (int o = 16; o > 0; o >>= 1) dot += __shfl_down_sync(0xffffffffu, dot, o);
    if (lane == 0) {
        float sg = 1.f / (1.f + expf(-dot));
        float t = neg ? logf(1.f - sg + 1e-15f) : logf(sg + 1e-15f);
        atomicAdd(&g_acc[neg ? 1 : 0], t);
    }
}

// ---------------- decoder aggregation ----------------
__global__ void k_rec_self() {
    int idx = blockIdx.x * blockDim.x + threadIdx.x;
    if (idx >= N_ * 32) return;
    int i = idx >> 5;
    float di = g_dinv[i];
    float w = g_ismask[i] ? 0.f : di * di;
    float4 v = *(const float4*)&g_REC0[(size_t)idx * 4];
    v.x *= w; v.y *= w; v.z *= w; v.w *= w;
    *(float4*)&g_RA[(size_t)idx * 4] = v;
}
__global__ void k_rec_edges(const int* __restrict__ ei) {
    int idx = blockIdx.x * blockDim.x + threadIdx.x;
    if (idx >= E_ * 32) return;
    int e = idx >> 5, c4 = (idx & 31) * 4;
    int s = ei[e], d = ei[E_ + e];
    if (g_ismask[s]) return;
    float w = g_dinv[s] * g_dinv[d];
    float4 v = *(const float4*)&g_REC0[(size_t)s * 128 + c4];
    v.x *= w; v.y *= w; v.z *= w; v.w *= w;
    red4(&g_RA[(size_t)d * 128 + c4], v);
}
__global__ void k_gather_ram(const int* __restrict__ perm) {
    int idx = blockIdx.x * blockDim.x + threadIdx.x;
    if (idx >= M_ * 32) return;
    int m = idx >> 5, c4 = (idx & 31) * 4;
    *(float4*)&g_RAM[(size_t)idx * 4] = *(const float4*)&g_RA[(size_t)perm[m] * 128 + c4];
}

// ---------------- feature (cosine) loss ----------------
__global__ void k_feat(const float* __restrict__ x, const int* __restrict__ perm) {
    __shared__ float shd[256], shx[256], shr[256];
    int m = blockIdx.x;
    int node = perm[m];
    const float* xr = x + (size_t)node * D_;
    const float* rr = g_RECM + (size_t)m * D_;
    float dt = 0.f, nx = 0.f, nr = 0.f;
    for (int d = threadIdx.x; d < D_; d += 256) {
        float a = xr[d], b = rr[d];
        dt += a * b; nx += a * a; nr += b * b;
    }
    shd[threadIdx.x] = dt; shx[threadIdx.x] = nx; shr[threadIdx.x] = nr;
    __syncthreads();
    for (int o = 128; o > 0; o >>= 1) {
        if (threadIdx.x < o) {
            shd[threadIdx.x] += shd[threadIdx.x + o];
            shx[threadIdx.x] += shx[threadIdx.x + o];
            shr[threadIdx.x] += shr[threadIdx.x + o];
        }
        __syncthreads();
    }
    if (threadIdx.x == 0) {
        float nxs = fmaxf(sqrtf(shx[0]), 1e-12f);
        float nrs = fmaxf(sqrtf(shr[0]), 1e-12f);
        float cs = shd[0] / (nxs * nrs);
        float t = 1.f - cs;
        atomicAdd(&g_acc[2], t * t);
    }
}
__global__ void k_final(float* __restrict__ out) {
    out[0] = g_acc[2] / (float)M_;
    out[1] = -(g_acc[0] + g_acc[1]) / (float)M_;
}

// ---------------- launch ----------------
extern "C" void kernel_launch(void* const* d_in, const int* in_sizes, int n_in,
                              void* d_out, int out_size) {
    const float* x    = (const float*)d_in[0];
    const int*   ei   = (const int*)  d_in[1];
    const int*   perm = (const int*)  d_in[2];
    const int*   shuf = (const int*)  d_in[3];
    const float* sW1  = (const float*)d_in[4];
    const float* sb1  = (const float*)d_in[5];
    const float* sa   = (const float*)d_in[6];
    const float* sW2  = (const float*)d_in[7];
    const float* sb2  = (const float*)d_in[8];
    const float* tW1  = (const float*)d_in[9];
    const float* tb1  = (const float*)d_in[10];
    const float* ta   = (const float*)d_in[11];
    const float* tW2  = (const float*)d_in[12];
    const float* tb2  = (const float*)d_in[13];
    const float* pW1  = (const float*)d_in[14];
    const float* pb1  = (const float*)d_in[15];
    const float* pa   = (const float*)d_in[16];
    const float* pW2  = (const float*)d_in[17];
    const float* pb2  = (const float*)d_in[18];
    const float* tpW1 = (const float*)d_in[19];
    const float* tpb1 = (const float*)d_in[20];
    const float* tpa  = (const float*)d_in[21];
    const float* tpW2 = (const float*)d_in[22];
    const float* tpb2 = (const float*)d_in[23];
    const float* dgiW = (const float*)d_in[24];
    const float* post = (const float*)d_in[25];
    const float* negt = (const float*)d_in[26];
    const float* e2d  = (const float*)d_in[27];
    const float* dW   = (const float*)d_in[28];
    const float* db   = (const float*)d_in[29];
    float* out = (float*)d_out;

    float *pXW1, *pH1, *pH2, *pREP, *pRM, *pZ1, *pZ, *pREC0, *pRAM, *pRECM;
    cudaGetSymbolAddress((void**)&pXW1,  g_XW1);
    cudaGetSymbolAddress((void**)&pH1,   g_H1);
    cudaGetSymbolAddress((void**)&pH2,   g_H2);
    cudaGetSymbolAddress((void**)&pREP,  g_REP);
    cudaGetSymbolAddress((void**)&pRM,   g_RM);
    cudaGetSymbolAddress((void**)&pZ1,   g_Z1);
    cudaGetSymbolAddress((void**)&pZ,    g_Z);
    cudaGetSymbolAddress((void**)&pREC0, g_REC0);
    cudaGetSymbolAddress((void**)&pRAM,  g_RAM);
    cudaGetSymbolAddress((void**)&pRECM, g_RECM);

    cudaFuncSetAttribute(k_mma_big, cudaFuncAttributeMaxDynamicSharedMemorySize, 99328);

    auto gemm = [&](int Mr, int Nc, int K, const float* A, int lda,
                    const float* B, int ldb, float* C, int ldc,
                    const float* bias, const float* alpha) {
        dim3 grid(CDIV(Nc, 128), CDIV(Mr, 128));
        k_sgemm<<<grid, 256>>>(Mr, Nc, K, A, lda, B, ldb, C, ldc, bias, alpha);
    };

    k_init_misc<<<CDIV(N_, 256), 256>>>();
    k_count_deg<<<CDIV(E_, 256), 256>>>(ei);
    k_dinv<<<CDIV(N_, 256), 256>>>();
    k_mask_map<<<CDIV(N_, 256), 256>>>(perm, shuf);
    k_token_w1<<<1024, 128>>>(post, negt, sW1, tW1);

    // big matmul: x @ [s_W1 | t_W1] via split-bf16 HMMA
    k_cvtA<<<(int)CDIV((size_t)N_ * KPAD, 256), 256>>>(x);
    k_cvtB<<<dim3(KPAD / 32, 1024 / 32), dim3(32, 8)>>>(sW1, tW1);
    k_mma_big<<<dim3(1024 / 256, CDIV(N_, 128)), 512, 99328>>>(pXW1);

    // layer-1 aggregation + bias + prelu
    k_agg1_self <<<CDIV(N_ * 256, 256), 256>>>();
    k_agg1_edges<<<CDIV(E_ * 256, 256), 256>>>(ei);
    k_bias_prelu1<<<CDIV(N_ * 256, 256), 256>>>(sb1, sa, tb1, ta);

    // layer-2 matmul + aggregation + bias + prelu
    gemm(N_, L_, H_, pH1, 1024, sW2, L_, pH2, 256, nullptr, nullptr);
    gemm(N_, L_, H_, pH1 + H_, 1024, tW2, L_, pH2 + L_, 256, nullptr, nullptr);
    k_agg2_self <<<CDIV(N_ * 64, 256), 256>>>();
    k_agg2_edges<<<CDIV(E_ * 64, 256), 256>>>(ei);
    k_bias_prelu2<<<CDIV(N_ * 64, 256), 256>>>(sb2, sa, tb2, ta);

    // projections on mask rows
    k_gather_rm<<<CDIV(M_ * 64, 256), 256>>>(perm);
    gemm(M_, P_, L_, pRM, 256, pW1, P_, pZ1, 512, pb1, pa);
    gemm(M_, P_, L_, pRM + L_, 256, tpW1, P_, pZ1 + P_, 512, tpb1, tpa);
    gemm(M_, L_, P_, pZ1, 512, pW2, L_, pZ, 256, pb2, nullptr);
    gemm(M_, L_, P_, pZ1 + P_, 512, tpW2, L_, pZ + L_, 256, tpb2, nullptr);

    // DGI loss
    k_colmean_sigmoid<<<128, 128>>>();
    k_ws<<<1, 128>>>(dgiW);
    k_dgi<<<CDIV(2 * M_ * 32, 256), 256>>>();

    // decoder
    gemm(N_, L_, L_, pREP, 256, e2d, L_, pREC0, 128, nullptr, nullptr);
    k_rec_self <<<CDIV(N_ * 32, 256), 256>>>();
    k_rec_edges<<<CDIV(E_ * 32, 256), 256>>>(ei);
    k_gather_ram<<<CDIV(M_ * 32, 256), 256>>>(perm);
    gemm(M_, D_, L_, pRAM, 128, dW, D_, pRECM, D_, db, nullptr);

    // feature loss + finalize
    k_feat<<<M_, 256>>>(x, perm);
    k_final<<<1, 1>>>(out);
}